// round 3
// baseline (speedup 1.0000x reference)
#include <cuda_runtime.h>

// AttributeBiasLoss — exact emulation of the reference's sequential fp32
// segment_sum (validated R2: rel_err 4.4e-6).
//   kA: fused per-node sigmoid-mean + per-chunk bin counts (transposed layout)
//   kB: per-bin prefix scan over chunks (contiguous reads) + bin bases
//   kC: stable scatter, 8 chunks per CTA (one per warp), match_any ranking
//   k3: per-bin sequential fp32 left-fold (order == reference scatter-add)
//   k4: fp32 means/diffs, final reduction

#define MAX_B      2097152
#define CHUNK      512
#define MAX_NCHUNK (MAX_B / CHUNK)   // 4096
#define NBIN       128
#define FOLD_BUF   4096

__device__ float    g_pernode[MAX_B];
__device__ float    g_sorted[MAX_B * 8];
__device__ unsigned g_counts[NBIN * MAX_NCHUNK];    // [bin][chunk]
__device__ unsigned g_chunkoff[NBIN * MAX_NCHUNK];  // [bin][chunk]
__device__ unsigned g_bintotal[NBIN];
__device__ unsigned g_binbase[NBIN];
__device__ float    g_binmean[NBIN];

__device__ __forceinline__ float ref_sigmoid(float x) {
    float e = expf(-x);
    return __fdiv_rn(1.0f, __fadd_rn(1.0f, e));
}

// ---------------- kA: fused per-node mean + per-chunk counts ---------------
__global__ void __launch_bounds__(256) kA_pernode_count(
    const float* __restrict__ pred, const int* __restrict__ attrs, int B)
{
    __shared__ unsigned cnt[NBIN];
    int tid = threadIdx.x;
    if (tid < NBIN) cnt[tid] = 0;
    __syncthreads();

    int start = blockIdx.x * CHUNK;
    int end   = min(start + CHUNK, B);
    for (int r = start + tid; r < end; r += 256) {
        const float4* p = reinterpret_cast<const float4*>(pred + (size_t)r * 8);
        float4 p0 = __ldg(p), p1 = __ldg(p + 1);
        float s = ref_sigmoid(p0.x);
        s = __fadd_rn(s, ref_sigmoid(p0.y));
        s = __fadd_rn(s, ref_sigmoid(p0.z));
        s = __fadd_rn(s, ref_sigmoid(p0.w));
        s = __fadd_rn(s, ref_sigmoid(p1.x));
        s = __fadd_rn(s, ref_sigmoid(p1.y));
        s = __fadd_rn(s, ref_sigmoid(p1.z));
        s = __fadd_rn(s, ref_sigmoid(p1.w));
        g_pernode[r] = __fmul_rn(s, 0.125f);

        const int4* a = reinterpret_cast<const int4*>(attrs + (size_t)r * 8);
        int4 a0 = __ldg(a), a1 = __ldg(a + 1);
        atomicAdd(&cnt[  0 + a0.x], 1u);
        atomicAdd(&cnt[ 16 + a0.y], 1u);
        atomicAdd(&cnt[ 32 + a0.z], 1u);
        atomicAdd(&cnt[ 48 + a0.w], 1u);
        atomicAdd(&cnt[ 64 + a1.x], 1u);
        atomicAdd(&cnt[ 80 + a1.y], 1u);
        atomicAdd(&cnt[ 96 + a1.z], 1u);
        atomicAdd(&cnt[112 + a1.w], 1u);
    }
    __syncthreads();
    if (tid < NBIN)
        g_counts[tid * MAX_NCHUNK + blockIdx.x] = cnt[tid];
}

// ---------------- kB: per-bin scan over chunks (contiguous) ----------------
__global__ void __launch_bounds__(128) kB_scan(int nchunk) {
    int t = threadIdx.x;    // bin
    const unsigned* src = &g_counts[t * MAX_NCHUNK];
    unsigned*       dst = &g_chunkoff[t * MAX_NCHUNK];
    unsigned run = 0;
    int c = 0;
    for (; c + 8 <= nchunk; c += 8) {
        unsigned v0 = src[c+0], v1 = src[c+1], v2 = src[c+2], v3 = src[c+3];
        unsigned v4 = src[c+4], v5 = src[c+5], v6 = src[c+6], v7 = src[c+7];
        dst[c+0] = run; run += v0;
        dst[c+1] = run; run += v1;
        dst[c+2] = run; run += v2;
        dst[c+3] = run; run += v3;
        dst[c+4] = run; run += v4;
        dst[c+5] = run; run += v5;
        dst[c+6] = run; run += v6;
        dst[c+7] = run; run += v7;
    }
    for (; c < nchunk; c++) { unsigned v = src[c]; dst[c] = run; run += v; }
    g_bintotal[t] = run;

    __shared__ unsigned tot[NBIN];
    __shared__ unsigned base[NBIN];
    tot[t] = run;
    __syncthreads();
    if (t == 0) {
        unsigned acc = 0;
        for (int i = 0; i < NBIN; i++) { base[i] = acc; acc += tot[i]; }
    }
    __syncthreads();
    g_binbase[t] = base[t];
}

// ---------------- kC: stable scatter, one chunk per warp -------------------
__global__ void __launch_bounds__(256) kC_scatter(
    const int* __restrict__ attrs, int B, int nchunk)
{
    __shared__ unsigned soff[8][NBIN];
    int wid  = threadIdx.x >> 5;
    int lane = threadIdx.x & 31;
    int chunk = blockIdx.x * 8 + wid;
    if (chunk >= nchunk) return;

    unsigned* off = soff[wid];
    for (int i = lane; i < NBIN; i += 32)
        off[i] = g_binbase[i] + g_chunkoff[i * MAX_NCHUNK + chunk];
    __syncwarp();

    int start = chunk * CHUNK;
    #pragma unroll 1
    for (int s = 0; s < CHUNK / 32; s++) {
        int  r   = start + s * 32 + lane;
        bool act = (r < B);
        float pn = 0.f;
        int v[8];
        if (act) {
            const int4* ap = reinterpret_cast<const int4*>(attrs + (size_t)r * 8);
            int4 a0 = __ldg(ap), a1 = __ldg(ap + 1);
            v[0] = a0.x; v[1] = a0.y; v[2] = a0.z; v[3] = a0.w;
            v[4] = a1.x; v[5] = a1.y; v[6] = a1.z; v[7] = a1.w;
            pn = g_pernode[r];
        } else {
            #pragma unroll
            for (int a = 0; a < 8; a++) v[a] = 16;   // sentinel
        }
        #pragma unroll
        for (int a = 0; a < 8; a++) {
            unsigned mask   = __match_any_sync(0xffffffffu, v[a]);
            unsigned rank   = __popc(mask & ((1u << lane) - 1u));
            int      leader = __ffs(mask) - 1;
            unsigned old    = 0;
            if (lane == leader && v[a] < 16) {
                int bin = a * 16 + v[a];
                old = off[bin];
                off[bin] = old + __popc(mask);
            }
            old = __shfl_sync(0xffffffffu, old, leader);
            if (act) g_sorted[old + rank] = pn;
        }
        __syncwarp();
    }
}

// ---------------- k3: per-bin sequential fp32 left-fold --------------------
__global__ void __launch_bounds__(64) k3_fold() {
    __shared__ float4 buf[2][FOLD_BUF / 4];
    int bin = blockIdx.x;
    int tid = threadIdx.x;
    unsigned n    = g_bintotal[bin];
    unsigned base = g_binbase[bin];
    int rounds = (int)((n + FOLD_BUF - 1) / FOLD_BUF);

    {   // prologue fill buf[0] (overreads stay inside g_sorted: B < MAX_B)
        float* dst = reinterpret_cast<float*>(buf[0]);
        for (int j = tid; j < FOLD_BUF; j += 64) dst[j] = g_sorted[base + j];
    }
    __syncthreads();

    float s = 0.0f;
    for (int r = 0; r < rounds; r++) {
        if (tid >= 32) {                       // prefetch warp
            if (r + 1 < rounds) {
                int l = tid - 32;
                unsigned o = base + (unsigned)(r + 1) * FOLD_BUF;
                float* dst = reinterpret_cast<float*>(buf[(r + 1) & 1]);
                #pragma unroll
                for (int j = 0; j < FOLD_BUF / 32; j++)
                    dst[j * 32 + l] = g_sorted[o + j * 32 + l];
            }
        } else if (tid == 0) {                 // serial fp32 chain
            const float4* b4 = buf[r & 1];
            const float*  bf = reinterpret_cast<const float*>(b4);
            int cnt = min(FOLD_BUF, (int)(n - (unsigned)r * FOLD_BUF));
            int i = 0;
            if (cnt >= 8) {
                float4 c0 = b4[0], c1 = b4[1];
                for (i = 0; i + 16 <= cnt; i += 8) {
                    float4 n0 = b4[i / 4 + 2], n1 = b4[i / 4 + 3];
                    s = __fadd_rn(s, c0.x); s = __fadd_rn(s, c0.y);
                    s = __fadd_rn(s, c0.z); s = __fadd_rn(s, c0.w);
                    s = __fadd_rn(s, c1.x); s = __fadd_rn(s, c1.y);
                    s = __fadd_rn(s, c1.z); s = __fadd_rn(s, c1.w);
                    c0 = n0; c1 = n1;
                }
                s = __fadd_rn(s, c0.x); s = __fadd_rn(s, c0.y);
                s = __fadd_rn(s, c0.z); s = __fadd_rn(s, c0.w);
                s = __fadd_rn(s, c1.x); s = __fadd_rn(s, c1.y);
                s = __fadd_rn(s, c1.z); s = __fadd_rn(s, c1.w);
                i += 8;
            }
            for (; i < cnt; i++) s = __fadd_rn(s, bf[i]);
        }
        __syncthreads();
    }
    if (tid == 0)
        g_binmean[bin] = (n > 0) ? __fdiv_rn(s, (float)n) : 0.0f;
}

// ---------------- k4: pairwise squared diffs --------------------------------
__global__ void __launch_bounds__(128) k4_final(float* __restrict__ out) {
    __shared__ float  m[NBIN];
    __shared__ int    pres[NBIN];
    __shared__ double sl[128];
    __shared__ int    sc[128];
    int t = threadIdx.x;
    m[t]    = g_binmean[t];
    pres[t] = (g_bintotal[t] > 0);
    __syncthreads();
    double loss = 0.0;
    int    ncmp = 0;
    for (int idx = t; idx < 8 * 256; idx += 128) {
        int aa = idx >> 8, i = (idx >> 4) & 15, j = idx & 15;
        if (j > i) {
            int bi = aa * 16 + i, bj = aa * 16 + j;
            if (pres[bi] && pres[bj]) {
                float d  = __fsub_rn(m[bi], m[bj]);
                float dd = __fmul_rn(d, d);
                loss += (double)dd;
                ncmp += 1;
            }
        }
    }
    sl[t] = loss; sc[t] = ncmp;
    __syncthreads();
    for (int o = 64; o > 0; o >>= 1) {
        if (t < o) { sl[t] += sl[t + o]; sc[t] += sc[t + o]; }
        __syncthreads();
    }
    if (t == 0)
        out[0] = (sc[0] > 0) ? (float)(sl[0] / (double)sc[0]) : 0.0f;
}

extern "C" void kernel_launch(void* const* d_in, const int* in_sizes, int n_in,
                              void* d_out, int out_size) {
    const float* pred  = (const float*)d_in[0];
    const int*   attrs = (const int*)d_in[1];
    int B = in_sizes[0] / 8;
    if (B > MAX_B) B = MAX_B;
    int nchunk = (B + CHUNK - 1) / CHUNK;

    kA_pernode_count<<<nchunk, 256>>>(pred, attrs, B);
    kB_scan<<<1, 128>>>(nchunk);
    kC_scatter<<<(nchunk + 7) / 8, 256>>>(attrs, B, nchunk);
    k3_fold<<<NBIN, 64>>>();
    k4_final<<<1, 128>>>((float*)d_out);
}

// round 4
// speedup vs baseline: 2.2209x; 2.2209x over previous
#include <cuda_runtime.h>

// AttributeBiasLoss — exact emulation of the reference's sequential fp32
// segment_sum (validated: rel_err 4.4e-6).
//   kA : fused per-node sigmoid-mean + per-chunk bin counts -> [bin][chunk]
//   kB : block-per-bin parallel scan (coalesced reads), writes [chunk][bin]
//   kB2: exclusive scan of bin totals -> bin bases
//   kC : stable scatter, one chunk per warp, match_any ranking
//   k3 : per-bin sequential fp32 left-fold (order == reference scatter-add)
//   k4 : fp32 means/diffs, final reduction

#define MAX_B      2097152
#define CHUNK      512
#define MAX_NCHUNK (MAX_B / CHUNK)   // 4096
#define NBIN       128
#define FOLD_BUF   4096

__device__ float    g_pernode[MAX_B];
__device__ float    g_sorted[MAX_B * 8];
__device__ unsigned g_counts[NBIN * MAX_NCHUNK];    // [bin][chunk] (kB reads coalesced)
__device__ unsigned g_chunkoff[MAX_NCHUNK * NBIN];  // [chunk][bin] (kC reads coalesced)
__device__ unsigned g_bintotal[NBIN];
__device__ unsigned g_binbase[NBIN];
__device__ float    g_binmean[NBIN];

__device__ __forceinline__ float ref_sigmoid(float x) {
    float e = expf(-x);
    return __fdiv_rn(1.0f, __fadd_rn(1.0f, e));
}

// ---------------- kA: fused per-node mean + per-chunk counts ---------------
__global__ void __launch_bounds__(256) kA_pernode_count(
    const float* __restrict__ pred, const int* __restrict__ attrs, int B)
{
    __shared__ unsigned cnt[NBIN];
    int tid = threadIdx.x;
    if (tid < NBIN) cnt[tid] = 0;
    __syncthreads();

    int start = blockIdx.x * CHUNK;
    int end   = min(start + CHUNK, B);
    for (int r = start + tid; r < end; r += 256) {
        const float4* p = reinterpret_cast<const float4*>(pred + (size_t)r * 8);
        float4 p0 = __ldg(p), p1 = __ldg(p + 1);
        float s = ref_sigmoid(p0.x);
        s = __fadd_rn(s, ref_sigmoid(p0.y));
        s = __fadd_rn(s, ref_sigmoid(p0.z));
        s = __fadd_rn(s, ref_sigmoid(p0.w));
        s = __fadd_rn(s, ref_sigmoid(p1.x));
        s = __fadd_rn(s, ref_sigmoid(p1.y));
        s = __fadd_rn(s, ref_sigmoid(p1.z));
        s = __fadd_rn(s, ref_sigmoid(p1.w));
        g_pernode[r] = __fmul_rn(s, 0.125f);

        const int4* a = reinterpret_cast<const int4*>(attrs + (size_t)r * 8);
        int4 a0 = __ldg(a), a1 = __ldg(a + 1);
        atomicAdd(&cnt[  0 + a0.x], 1u);
        atomicAdd(&cnt[ 16 + a0.y], 1u);
        atomicAdd(&cnt[ 32 + a0.z], 1u);
        atomicAdd(&cnt[ 48 + a0.w], 1u);
        atomicAdd(&cnt[ 64 + a1.x], 1u);
        atomicAdd(&cnt[ 80 + a1.y], 1u);
        atomicAdd(&cnt[ 96 + a1.z], 1u);
        atomicAdd(&cnt[112 + a1.w], 1u);
    }
    __syncthreads();
    if (tid < NBIN)
        g_counts[(size_t)tid * MAX_NCHUNK + blockIdx.x] = cnt[tid];
}

// ---------------- kB: block-per-bin parallel scan ---------------------------
__global__ void __launch_bounds__(128) kB_scan(int nchunk) {
    int bin  = blockIdx.x;
    int t    = threadIdx.x;
    int lane = t & 31, wid = t >> 5;
    const unsigned* src = &g_counts[(size_t)bin * MAX_NCHUNK];
    __shared__ unsigned wsum[4];

    unsigned run = 0;
    for (int c0 = 0; c0 < nchunk; c0 += 128) {
        int c = c0 + t;
        unsigned v = (c < nchunk) ? src[c] : 0u;
        unsigned x = v;
        #pragma unroll
        for (int o = 1; o < 32; o <<= 1) {
            unsigned y = __shfl_up_sync(0xffffffffu, x, o);
            if (lane >= o) x += y;
        }
        if (lane == 31) wsum[wid] = x;
        __syncthreads();
        unsigned woff = 0;
        #pragma unroll
        for (int w = 0; w < 4; w++) if (w < wid) woff += wsum[w];
        if (c < nchunk)
            g_chunkoff[(size_t)c * NBIN + bin] = run + woff + x - v;
        unsigned btot = wsum[0] + wsum[1] + wsum[2] + wsum[3];
        __syncthreads();
        run += btot;
    }
    if (t == 0) g_bintotal[bin] = run;
}

// ---------------- kB2: bin bases (exclusive scan of 128 totals) ------------
__global__ void __launch_bounds__(128) kB2_base() {
    int t    = threadIdx.x;
    int lane = t & 31, wid = t >> 5;
    __shared__ unsigned wsum[4];
    unsigned v = g_bintotal[t];
    unsigned x = v;
    #pragma unroll
    for (int o = 1; o < 32; o <<= 1) {
        unsigned y = __shfl_up_sync(0xffffffffu, x, o);
        if (lane >= o) x += y;
    }
    if (lane == 31) wsum[wid] = x;
    __syncthreads();
    unsigned woff = 0;
    #pragma unroll
    for (int w = 0; w < 4; w++) if (w < wid) woff += wsum[w];
    g_binbase[t] = woff + x - v;
}

// ---------------- kC: stable scatter, one chunk per warp -------------------
__global__ void __launch_bounds__(256) kC_scatter(
    const int* __restrict__ attrs, int B, int nchunk)
{
    __shared__ unsigned soff[8][NBIN];
    int wid  = threadIdx.x >> 5;
    int lane = threadIdx.x & 31;
    int chunk = blockIdx.x * 8 + wid;
    if (chunk >= nchunk) return;

    unsigned* off = soff[wid];
    for (int i = lane; i < NBIN; i += 32)
        off[i] = g_binbase[i] + g_chunkoff[(size_t)chunk * NBIN + i];
    __syncwarp();

    int start = chunk * CHUNK;
    #pragma unroll 1
    for (int s = 0; s < CHUNK / 32; s++) {
        int  r   = start + s * 32 + lane;
        bool act = (r < B);
        float pn = 0.f;
        int v[8];
        if (act) {
            const int4* ap = reinterpret_cast<const int4*>(attrs + (size_t)r * 8);
            int4 a0 = __ldg(ap), a1 = __ldg(ap + 1);
            v[0] = a0.x; v[1] = a0.y; v[2] = a0.z; v[3] = a0.w;
            v[4] = a1.x; v[5] = a1.y; v[6] = a1.z; v[7] = a1.w;
            pn = g_pernode[r];
        } else {
            #pragma unroll
            for (int a = 0; a < 8; a++) v[a] = 16;   // sentinel
        }
        #pragma unroll
        for (int a = 0; a < 8; a++) {
            unsigned mask   = __match_any_sync(0xffffffffu, v[a]);
            unsigned rank   = __popc(mask & ((1u << lane) - 1u));
            int      leader = __ffs(mask) - 1;
            unsigned old    = 0;
            if (lane == leader && v[a] < 16) {
                int bin = a * 16 + v[a];
                old = off[bin];
                off[bin] = old + __popc(mask);
            }
            old = __shfl_sync(0xffffffffu, old, leader);
            if (act) g_sorted[old + rank] = pn;
        }
        __syncwarp();
    }
}

// ---------------- k3: per-bin sequential fp32 left-fold --------------------
__global__ void __launch_bounds__(64) k3_fold() {
    __shared__ float4 buf[2][FOLD_BUF / 4];
    int bin = blockIdx.x;
    int tid = threadIdx.x;
    unsigned n    = g_bintotal[bin];
    unsigned base = g_binbase[bin];
    int rounds = (int)((n + FOLD_BUF - 1) / FOLD_BUF);

    {   // prologue fill buf[0] (overreads stay inside g_sorted: B < MAX_B)
        float* dst = reinterpret_cast<float*>(buf[0]);
        for (int j = tid; j < FOLD_BUF; j += 64) dst[j] = g_sorted[base + j];
    }
    __syncthreads();

    float s = 0.0f;
    for (int r = 0; r < rounds; r++) {
        if (tid >= 32) {                       // prefetch warp
            if (r + 1 < rounds) {
                int l = tid - 32;
                unsigned o = base + (unsigned)(r + 1) * FOLD_BUF;
                float* dst = reinterpret_cast<float*>(buf[(r + 1) & 1]);
                #pragma unroll
                for (int j = 0; j < FOLD_BUF / 32; j++)
                    dst[j * 32 + l] = g_sorted[o + j * 32 + l];
            }
        } else if (tid == 0) {                 // serial fp32 chain
            const float4* b4 = buf[r & 1];
            const float*  bf = reinterpret_cast<const float*>(b4);
            int cnt = min(FOLD_BUF, (int)(n - (unsigned)r * FOLD_BUF));
            int i = 0;
            if (cnt >= 8) {
                float4 c0 = b4[0], c1 = b4[1];
                for (i = 0; i + 16 <= cnt; i += 8) {
                    float4 n0 = b4[i / 4 + 2], n1 = b4[i / 4 + 3];
                    s = __fadd_rn(s, c0.x); s = __fadd_rn(s, c0.y);
                    s = __fadd_rn(s, c0.z); s = __fadd_rn(s, c0.w);
                    s = __fadd_rn(s, c1.x); s = __fadd_rn(s, c1.y);
                    s = __fadd_rn(s, c1.z); s = __fadd_rn(s, c1.w);
                    c0 = n0; c1 = n1;
                }
                s = __fadd_rn(s, c0.x); s = __fadd_rn(s, c0.y);
                s = __fadd_rn(s, c0.z); s = __fadd_rn(s, c0.w);
                s = __fadd_rn(s, c1.x); s = __fadd_rn(s, c1.y);
                s = __fadd_rn(s, c1.z); s = __fadd_rn(s, c1.w);
                i += 8;
            }
            for (; i < cnt; i++) s = __fadd_rn(s, bf[i]);
        }
        __syncthreads();
    }
    if (tid == 0)
        g_binmean[bin] = (n > 0) ? __fdiv_rn(s, (float)n) : 0.0f;
}

// ---------------- k4: pairwise squared diffs --------------------------------
__global__ void __launch_bounds__(128) k4_final(float* __restrict__ out) {
    __shared__ float  m[NBIN];
    __shared__ int    pres[NBIN];
    __shared__ double sl[128];
    __shared__ int    sc[128];
    int t = threadIdx.x;
    m[t]    = g_binmean[t];
    pres[t] = (g_bintotal[t] > 0);
    __syncthreads();
    double loss = 0.0;
    int    ncmp = 0;
    for (int idx = t; idx < 8 * 256; idx += 128) {
        int aa = idx >> 8, i = (idx >> 4) & 15, j = idx & 15;
        if (j > i) {
            int bi = aa * 16 + i, bj = aa * 16 + j;
            if (pres[bi] && pres[bj]) {
                float d  = __fsub_rn(m[bi], m[bj]);
                float dd = __fmul_rn(d, d);
                loss += (double)dd;
                ncmp += 1;
            }
        }
    }
    sl[t] = loss; sc[t] = ncmp;
    __syncthreads();
    for (int o = 64; o > 0; o >>= 1) {
        if (t < o) { sl[t] += sl[t + o]; sc[t] += sc[t + o]; }
        __syncthreads();
    }
    if (t == 0)
        out[0] = (sc[0] > 0) ? (float)(sl[0] / (double)sc[0]) : 0.0f;
}

extern "C" void kernel_launch(void* const* d_in, const int* in_sizes, int n_in,
                              void* d_out, int out_size) {
    const float* pred  = (const float*)d_in[0];
    const int*   attrs = (const int*)d_in[1];
    int B = in_sizes[0] / 8;
    if (B > MAX_B) B = MAX_B;
    int nchunk = (B + CHUNK - 1) / CHUNK;

    kA_pernode_count<<<nchunk, 256>>>(pred, attrs, B);
    kB_scan<<<NBIN, 128>>>(nchunk);
    kB2_base<<<1, 128>>>();
    kC_scatter<<<(nchunk + 7) / 8, 256>>>(attrs, B, nchunk);
    k3_fold<<<NBIN, 64>>>();
    k4_final<<<1, 128>>>((float*)d_out);
}